// round 15
// baseline (speedup 1.0000x reference)
#include <cuda_runtime.h>
#include <cuda_fp16.h>
#include <cstdint>

#define N_NODES 20000
#define N_EDGES 100000
#define DN 256
#define DE 256
#define DH 512
#define NLAYERS 2

// ---------------- scratch (device globals: allocation-free) ----------------
// all GEMM operands single fp16
__device__ __align__(16) uint16_t g_m1f [(size_t)N_EDGES * DH];
__device__ __align__(16) uint16_t g_ef  [(size_t)N_EDGES * DE];
__device__ __align__(16) uint16_t g_xf  [(size_t)N_NODES * DN];
__device__ __align__(16) uint16_t g_aggf[(size_t)N_NODES * DH];
__device__ __align__(16) uint16_t g_hf  [(size_t)N_NODES * DH];
__device__ float g_x  [(size_t)N_NODES * DN];   // fp32 x for residual
__device__ float g_agg[(size_t)N_NODES * DH];   // fp32 atomics accumulator
__device__ float g_cnt[N_NODES];

// transposed fp16 weights [N][K] K-major, per layer
#define OFF_W1A 0
#define OFF_W1B (DH * (2 * DN + DE))
#define OFF_W2A (OFF_W1B + (2 * DH + DE) * DH)
#define OFF_W2B (OFF_W2A + DH * DH)
#define WT_LAYER (OFF_W2B + DH * DN)
__device__ __align__(16) uint16_t g_Wf[(size_t)NLAYERS * WT_LAYER];

// ---------------- helpers ----------------
__device__ __forceinline__ uint32_t smem_to_u32(const void* p) {
    uint32_t a;
    asm("{ .reg .u64 t; cvta.to.shared.u64 t, %1; cvt.u32.u64 %0, t; }"
        : "=r"(a) : "l"(p));
    return a;
}

// pack (x, y) -> fp16x2, x in low half
__device__ __forceinline__ uint32_t f16x2(float x, float y) {
    uint32_t r;
    asm("cvt.rn.f16x2.f32 %0, %1, %2;" : "=r"(r) : "f"(y), "f"(x));
    return r;
}

__device__ __forceinline__ void cp16(uint32_t dst, const void* src) {
    asm volatile("cp.async.ca.shared.global [%0], [%1], 16;"
                 :: "r"(dst), "l"(src) : "memory");
}
#define CP_COMMIT() asm volatile("cp.async.commit_group;" ::: "memory")
#define CP_WAIT2()  asm volatile("cp.async.wait_group 2;" ::: "memory")
#define CP_WAIT1()  asm volatile("cp.async.wait_group 1;" ::: "memory")
#define CP_WAIT0()  asm volatile("cp.async.wait_group 0;" ::: "memory")

__device__ __forceinline__ void ldsm4(uint32_t addr, uint32_t* r) {
    asm volatile("ldmatrix.sync.aligned.m8n8.x4.shared.b16 {%0,%1,%2,%3}, [%4];"
                 : "=r"(r[0]), "=r"(r[1]), "=r"(r[2]), "=r"(r[3]) : "r"(addr));
}

__device__ __forceinline__ void mma_f16(float* c, const uint32_t* a,
                                        uint32_t b0, uint32_t b1) {
    asm volatile("mma.sync.aligned.m16n8k16.row.col.f32.f16.f16.f32 "
                 "{%0,%1,%2,%3}, {%4,%5,%6,%7}, {%8,%9}, {%0,%1,%2,%3};"
                 : "+f"(c[0]), "+f"(c[1]), "+f"(c[2]), "+f"(c[3])
                 : "r"(a[0]), "r"(a[1]), "r"(a[2]), "r"(a[3]), "r"(b0), "r"(b1));
}

__device__ __forceinline__ void red_add_v2(float* p, float x, float y) {
    asm volatile("red.global.add.v2.f32 [%0], {%1, %2};"
                 :: "l"(p), "f"(x), "f"(y) : "memory");
}

// ---------------- dynamic smem layout ----------------
#define SM_BIAS   0       // 128 floats
#define SM_DST    512     // 128 ints
#define SM_SRC    1024
#define SM_TILES  2048
#define PITCH     80                    // 64B fp16 row + 16B pad (ldmatrix conflict-free)
#define TILE_B    (128 * PITCH)         // 10240
#define STAGE_B   (2 * TILE_B)          // A, B
#define NSTAGE    4
#define SMEM_TOTAL (SM_TILES + NSTAGE * STAGE_B)  // 83968 -> still 2 CTAs/SM (168KB/228KB)

// ---------------- utility kernels ----------------
__global__ void zero_cnt_kernel() {
    int i = blockIdx.x * blockDim.x + threadIdx.x;
    if (i < N_NODES) g_cnt[i] = 0.f;
}
__global__ void zero_agg_kernel() {
    int i = blockIdx.x * blockDim.x + threadIdx.x;
    if (i < N_NODES * DH / 4)
        ((float4*)g_agg)[i] = make_float4(0.f, 0.f, 0.f, 0.f);
}
__global__ void count_kernel(const int* __restrict__ dstI) {
    int e = blockIdx.x * blockDim.x + threadIdx.x;
    if (e < N_EDGES) atomicAdd(&g_cnt[dstI[e]], 1.f);
}

// fp32 -> fp16 for both inputs in one launch
#define NPX (N_NODES * DN / 2)
#define NPE (N_EDGES * DE / 2)
__global__ void round_inputs_kernel(const float* __restrict__ node,
                                    const float* __restrict__ edge,
                                    uint16_t* __restrict__ xf,
                                    uint16_t* __restrict__ ef) {
    int i = blockIdx.x * blockDim.x + threadIdx.x;
    if (i < NPX) {
        float2 v = ((const float2*)node)[i];
        ((uint32_t*)xf)[i] = f16x2(v.x, v.y);
    } else if (i < NPX + NPE) {
        int j = i - NPX;
        float2 v = ((const float2*)edge)[j];
        ((uint32_t*)ef)[j] = f16x2(v.x, v.y);
    }
}

// agg: normalize by 1/max(cnt,1), round to fp16
__global__ void norm_agg_kernel() {
    int i = blockIdx.x * blockDim.x + threadIdx.x;
    if (i < N_NODES * DH / 2) {
        int row = i >> 8;  // 256 pairs per row
        float s = 1.f / fmaxf(g_cnt[row], 1.f);
        float2 v = ((const float2*)g_agg)[i];
        ((uint32_t*)g_aggf)[i] = f16x2(v.x * s, v.y * s);
    }
}

// ALL weight transposes in one launch.
// W [K][N] row-major -> Wf [N][K] fp16.  All dims multiples of 32.
// tiles/layer: W1a 24x16=384, W1b 16x40=640, W2a 16x16=256, W2b 16x8=128; cum 1408.
#define T_CUM1 384
#define T_CUM2 1024
#define T_CUM3 1280
#define T_TOTAL 1408
__global__ void transpose_all_kernel(const float* __restrict__ W1a,
                                     const float* __restrict__ W1b,
                                     const float* __restrict__ W2a,
                                     const float* __restrict__ W2b,
                                     uint16_t* __restrict__ wf) {
    __shared__ float t[32][33];
    const int l = blockIdx.y;
    int f = blockIdx.x;
    const float* src;
    int K, N, off;
    if (f < T_CUM1)      { src = W1a + (size_t)l * 768 * 512;   K = 768; N = 512;  off = OFF_W1A; }
    else if (f < T_CUM2) { f -= T_CUM1; src = W1b + (size_t)l * 512 * 1280; K = 512; N = 1280; off = OFF_W1B; }
    else if (f < T_CUM3) { f -= T_CUM2; src = W2a + (size_t)l * 512 * 512;  K = 512; N = 512;  off = OFF_W2A; }
    else                 { f -= T_CUM3; src = W2b + (size_t)l * 512 * 256;  K = 512; N = 256;  off = OFF_W2B; }
    const int tilesN = N / 32;
    const int by = (f / tilesN) * 32;   // K tile
    const int bx = (f % tilesN) * 32;   // N tile
    uint16_t* dst = wf + (size_t)l * WT_LAYER + off;
    const int tx = threadIdx.x, ty = threadIdx.y;
#pragma unroll
    for (int j = 0; j < 32; j += 8)
        t[ty + j][tx] = src[(size_t)(by + ty + j) * N + bx + tx];
    __syncthreads();
#pragma unroll
    for (int j = 0; j < 32; j += 8)
        dst[(size_t)(bx + ty + j) * K + by + tx] =
            __half_as_ushort(__float2half_rn(t[tx][ty + j]));
}

// ---------------- fp16 mma.sync mainloop, cp.async 4-stage, 1 barrier/chunk -
// 128x128 CTA tile, BK=32, 8 warps (4M x 2N), warp tile 32x64.
template <int KDIM, class AS>
__device__ __forceinline__ void mainloop_mma(
    char* smem, const uint16_t* __restrict__ Wf,
    int n0, AS asrc, float C[2][8][4])
{
    const int tid = threadIdx.x;
    const int lane = tid & 31, warp = tid >> 5;
    const int wm = warp & 3, wn = warp >> 2;
    const uint32_t sb = smem_to_u32(smem);
    constexpr int NC = KDIM / 32;
    static_assert(NC >= 3, "pipeline depth");

    auto issue = [&](int c) {
        const int st = c & (NSTAGE - 1);
        const uint32_t base = sb + SM_TILES + st * STAGE_B;
#pragma unroll
        for (int halfp = 0; halfp < 2; ++halfp) {
            int id = tid + halfp * 256;
            int row = id >> 2, seg = id & 3;
            int kg = c * 32 + seg * 8;
            uint32_t off = (uint32_t)row * PITCH + seg * 16;
            cp16(base + off, asrc(row, kg));
            cp16(base + TILE_B + off, Wf + (size_t)(n0 + row) * KDIM + kg);
        }
        CP_COMMIT();
    };

    issue(0); issue(1); issue(2);

    const int lrow = lane & 15;
    const int lk = (lane >> 4) * 16;

    for (int c = 0; c < NC; ++c) {
        int rem = NC - 1 - c;
        if (rem >= 2) CP_WAIT2(); else if (rem == 1) CP_WAIT1(); else CP_WAIT0();
        __syncthreads();
        // issue into stage (c+3)%4 == (c-1)%4: its readers finished last
        // iteration's compute, proven by the barrier above. Single barrier.
        if (c + 3 < NC) issue(c + 3);

        const int st = c & (NSTAGE - 1);
        const uint32_t sA = sb + SM_TILES + st * STAGE_B;
        const uint32_t sB = sA + TILE_B;
#pragma unroll
        for (int ks = 0; ks < 2; ++ks) {
            uint32_t a[2][4];
#pragma unroll
            for (int i = 0; i < 2; ++i) {
                uint32_t ao = (uint32_t)(32 * wm + 16 * i + lrow) * PITCH + ks * 32 + lk;
                ldsm4(sA + ao, a[i]);
            }
#pragma unroll
            for (int g = 0; g < 4; ++g) {
                uint32_t bo = (uint32_t)(64 * wn + 16 * g + lrow) * PITCH + ks * 32 + lk;
                uint32_t b[4];
                ldsm4(sB + bo, b);
#pragma unroll
                for (int i = 0; i < 2; ++i) {
                    mma_f16(C[i][2 * g],     a[i], b[0], b[2]);
                    mma_f16(C[i][2 * g + 1], a[i], b[1], b[3]);
                }
            }
        }
    }
    __syncthreads();
}

#define ZERO_C() \
    float C[2][8][4]; \
    _Pragma("unroll") for (int i = 0; i < 2; ++i) \
    _Pragma("unroll") for (int j = 0; j < 8; ++j) \
    _Pragma("unroll") for (int q = 0; q < 4; ++q) C[i][j][q] = 0.f;

// ============================================================================
// GEMM1: m1 = relu([x[dst]|e|x[src]] @ W1a + b1a) -> fp16 m1f
// ============================================================================
__global__ void __launch_bounds__(256, 2) g1_kernel(
    const int* __restrict__ srcI, const int* __restrict__ dstI,
    const uint16_t* __restrict__ Wf, const float* __restrict__ bias)
{
    extern __shared__ char smem[];
    const int tid = threadIdx.x;
    const int n0 = blockIdx.x * 128, m0 = blockIdx.y * 128;
    float* biasS = (float*)(smem + SM_BIAS);
    int* sDst = (int*)(smem + SM_DST);
    int* sSrc = (int*)(smem + SM_SRC);
    if (tid < 128) {
        biasS[tid] = bias[n0 + tid];
        int r = min(m0 + tid, N_EDGES - 1);
        sDst[tid] = dstI[r];
        sSrc[tid] = srcI[r];
    }
    __syncthreads();

    ZERO_C();
    auto asrc = [&](int row, int kg) -> const uint16_t* {
        int r = min(m0 + row, N_EDGES - 1);
        if (kg < DN)      return g_xf + (size_t)sDst[row] * DN + kg;
        if (kg < DN + DE) return g_ef + (size_t)r * DE + (kg - DN);
        return g_xf + (size_t)sSrc[row] * DN + (kg - DN - DE);
    };
    mainloop_mma<2 * DN + DE>(smem, Wf, n0, asrc, C);

    const int lane = tid & 31, warp = tid >> 5;
    const int wm = warp & 3, wn = warp >> 2;
#pragma unroll
    for (int i = 0; i < 2; ++i)
#pragma unroll
    for (int h = 0; h < 2; ++h) {
        int rl = 32 * wm + 16 * i + 8 * h + (lane >> 2);
        int r = m0 + rl;
        if (r >= N_EDGES) continue;
#pragma unroll
        for (int j = 0; j < 8; ++j) {
            int cl = 64 * wn + 8 * j + 2 * (lane & 3);
            float ox = fmaxf(C[i][j][2 * h + 0] + biasS[cl + 0], 0.f);
            float oy = fmaxf(C[i][j][2 * h + 1] + biasS[cl + 1], 0.f);
            ((uint32_t*)g_m1f)[((size_t)r * DH + n0 + cl) >> 1] = f16x2(ox, oy);
        }
    }
}

// ============================================================================
// GEMM2: relu(m1 @ W1b + b1b)   (E x 512)@(512 x 1280)
// cols [0,512)+[768,1280) -> red.v2 into g_agg[dst]; [512,768) -> new_e
// ============================================================================
__global__ void __launch_bounds__(256, 2) g2_kernel(
    const int* __restrict__ dstI,
    const uint16_t* __restrict__ Wf, const float* __restrict__ bias,
    float* __restrict__ eoutF, int last)
{
    extern __shared__ char smem[];
    const int tid = threadIdx.x;
    const int n0 = blockIdx.x * 128, m0 = blockIdx.y * 128;
    float* biasS = (float*)(smem + SM_BIAS);
    int* sDst = (int*)(smem + SM_DST);
    if (tid < 128) {
        biasS[tid] = bias[n0 + tid];
        sDst[tid] = dstI[min(m0 + tid, N_EDGES - 1)];
    }
    __syncthreads();

    ZERO_C();
    auto asrc = [&](int row, int kg) -> const uint16_t* {
        size_t r = (size_t)min(m0 + row, N_EDGES - 1);
        return g_m1f + r * DH + kg;
    };
    mainloop_mma<DH>(smem, Wf, n0, asrc, C);

    const int lane = tid & 31, warp = tid >> 5;
    const int wm = warp & 3, wn = warp >> 2;
    const int mode = (n0 < DH) ? 0 : ((n0 < DH + DE) ? 1 : 2);
    const int aggc0 = (mode == 2) ? (n0 - DH - DE) : n0;
#pragma unroll
    for (int i = 0; i < 2; ++i)
#pragma unroll
    for (int h = 0; h < 2; ++h) {
        int rl = 32 * wm + 16 * i + 8 * h + (lane >> 2);
        int r = m0 + rl;
        if (r >= N_EDGES) continue;
        int dn = sDst[rl];
#pragma unroll
        for (int j = 0; j < 8; ++j) {
            int cl = 64 * wn + 8 * j + 2 * (lane & 3);
            float ox = fmaxf(C[i][j][2 * h + 0] + biasS[cl + 0], 0.f);
            float oy = fmaxf(C[i][j][2 * h + 1] + biasS[cl + 1], 0.f);
            if (mode == 1) {
                size_t eoff = (size_t)r * DE + (n0 - DH) + cl;
                if (last) *(float2*)(eoutF + eoff) = make_float2(ox, oy);
                else      ((uint32_t*)g_ef)[eoff >> 1] = f16x2(ox, oy);
            } else {
                red_add_v2(g_agg + (size_t)dn * DH + aggc0 + cl, ox, oy);
            }
        }
    }
}

// ============================================================================
// GEMM3: h = relu(aggn @ W2a + b2a) -> fp16 hf   (N x 512)@(512 x 512)
// ============================================================================
__global__ void __launch_bounds__(256, 2) g3_kernel(
    const uint16_t* __restrict__ Wf, const float* __restrict__ bias)
{
    extern __shared__ char smem[];
    const int tid = threadIdx.x;
    const int n0 = blockIdx.x * 128, m0 = blockIdx.y * 128;
    float* biasS = (float*)(smem + SM_BIAS);
    if (tid < 128) biasS[tid] = bias[n0 + tid];
    __syncthreads();

    ZERO_C();
    auto asrc = [&](int row, int kg) -> const uint16_t* {
        size_t r = (size_t)min(m0 + row, N_NODES - 1);
        return g_aggf + r * DH + kg;
    };
    mainloop_mma<DH>(smem, Wf, n0, asrc, C);

    const int lane = tid & 31, warp = tid >> 5;
    const int wm = warp & 3, wn = warp >> 2;
#pragma unroll
    for (int i = 0; i < 2; ++i)
#pragma unroll
    for (int h = 0; h < 2; ++h) {
        int rl = 32 * wm + 16 * i + 8 * h + (lane >> 2);
        int r = m0 + rl;
        if (r >= N_NODES) continue;
#pragma unroll
        for (int j = 0; j < 8; ++j) {
            int cl = 64 * wn + 8 * j + 2 * (lane & 3);
            float ox = fmaxf(C[i][j][2 * h + 0] + biasS[cl + 0], 0.f);
            float oy = fmaxf(C[i][j][2 * h + 1] + biasS[cl + 1], 0.f);
            ((uint32_t*)g_hf)[((size_t)r * DH + n0 + cl) >> 1] = f16x2(ox, oy);
        }
    }
}

// ============================================================================
// GEMM4: new_x = x + (h @ W2b + b2b)  [+relu, + fp16 copy for next layer]
// ============================================================================
__global__ void __launch_bounds__(256, 2) g4_kernel(
    const float* __restrict__ xin,
    const uint16_t* __restrict__ Wf, const float* __restrict__ bias,
    float* __restrict__ xoutF, int last)
{
    extern __shared__ char smem[];
    const int tid = threadIdx.x;
    const int n0 = blockIdx.x * 128, m0 = blockIdx.y * 128;
    float* biasS = (float*)(smem + SM_BIAS);
    if (tid < 128) biasS[tid] = bias[n0 + tid];
    __syncthreads();

    ZERO_C();
    auto asrc = [&](int row, int kg) -> const uint16_t* {
        size_t r = (size_t)min(m0 + row, N_NODES - 1);
        return g_hf + r * DH + kg;
    };
    mainloop_mma<DH>(smem, Wf, n0, asrc, C);

    const int lane = tid & 31, warp = tid >> 5;
    const int wm = warp & 3, wn = warp >> 2;
#pragma unroll
    for (int i = 0; i < 2; ++i)
#pragma unroll
    for (int h = 0; h < 2; ++h) {
        int rl = 32 * wm + 16 * i + 8 * h + (lane >> 2);
        int r = m0 + rl;
        if (r >= N_NODES) continue;
        const float* xrow = xin + (size_t)r * DN + n0;
#pragma unroll
        for (int j = 0; j < 8; ++j) {
            int cl = 64 * wn + 8 * j + 2 * (lane & 3);
            float2 xv = *(const float2*)(xrow + cl);
            float ox = C[i][j][2 * h + 0] + biasS[cl + 0] + xv.x;
            float oy = C[i][j][2 * h + 1] + biasS[cl + 1] + xv.y;
            size_t xoff = (size_t)r * DN + n0 + cl;
            if (last) {
                *(float2*)(xoutF + xoff) = make_float2(ox, oy);
            } else {
                ox = fmaxf(ox, 0.f); oy = fmaxf(oy, 0.f);
                *(float2*)(xoutF + xoff) = make_float2(ox, oy);
                ((uint32_t*)g_xf)[xoff >> 1] = f16x2(ox, oy);
            }
        }
    }
}

// ============================================================================
extern "C" void kernel_launch(void* const* d_in, const int* in_sizes, int n_in,
                              void* d_out, int out_size)
{
    (void)in_sizes; (void)n_in; (void)out_size;
    const float* node = (const float*)d_in[0];
    const float* edge = (const float*)d_in[1];
    const int*   eidx = (const int*)  d_in[2];
    const float* W1a  = (const float*)d_in[3];
    const float* b1a  = (const float*)d_in[4];
    const float* W1b  = (const float*)d_in[5];
    const float* b1b  = (const float*)d_in[6];
    const float* W2a  = (const float*)d_in[7];
    const float* b2a  = (const float*)d_in[8];
    const float* W2b  = (const float*)d_in[9];
    const float* b2b  = (const float*)d_in[10];
    float* out = (float*)d_out;

    const int* srcI = eidx;
    const int* dstI = eidx + N_EDGES;

    cudaFuncSetAttribute(g1_kernel, cudaFuncAttributeMaxDynamicSharedMemorySize, SMEM_TOTAL);
    cudaFuncSetAttribute(g2_kernel, cudaFuncAttributeMaxDynamicSharedMemorySize, SMEM_TOTAL);
    cudaFuncSetAttribute(g3_kernel, cudaFuncAttributeMaxDynamicSharedMemorySize, SMEM_TOTAL);
    cudaFuncSetAttribute(g4_kernel, cudaFuncAttributeMaxDynamicSharedMemorySize, SMEM_TOTAL);

    void* t;
    cudaGetSymbolAddress(&t, g_x);  float* p_gx = (float*)t;
    cudaGetSymbolAddress(&t, g_xf); uint16_t* p_xf = (uint16_t*)t;
    cudaGetSymbolAddress(&t, g_ef); uint16_t* p_ef = (uint16_t*)t;
    cudaGetSymbolAddress(&t, g_Wf); uint16_t* p_wf = (uint16_t*)t;

    // setup: 4 launches total
    round_inputs_kernel<<<(NPX + NPE + 255) / 256, 256>>>(node, edge, p_xf, p_ef);
    transpose_all_kernel<<<dim3(T_TOTAL, NLAYERS), dim3(32, 8)>>>(
        W1a, W1b, W2a, W2b, p_wf);
    zero_cnt_kernel<<<(N_NODES + 255) / 256, 256>>>();
    count_kernel<<<(N_EDGES + 255) / 256, 256>>>(dstI);

    const int MT_E = (N_EDGES + 127) / 128;  // 782
    const int MT_N = (N_NODES + 127) / 128;  // 157

    for (int l = 0; l < NLAYERS; ++l) {
        const int last = (l == NLAYERS - 1) ? 1 : 0;
        size_t base = (size_t)l * WT_LAYER;

        zero_agg_kernel<<<(N_NODES * DH / 4 + 255) / 256, 256>>>();

        g1_kernel<<<dim3(DH / 128, MT_E), 256, SMEM_TOTAL>>>(
            srcI, dstI, p_wf + base + OFF_W1A, b1a + (size_t)l * DH);

        g2_kernel<<<dim3((2 * DH + DE) / 128, MT_E), 256, SMEM_TOTAL>>>(
            dstI, p_wf + base + OFF_W1B, b1b + (size_t)l * (2 * DH + DE),
            last ? (out + (size_t)N_NODES * DN) : nullptr, last);

        norm_agg_kernel<<<(N_NODES * DH / 2 + 255) / 256, 256>>>();

        g3_kernel<<<dim3(DH / 128, MT_N), 256, SMEM_TOTAL>>>(
            p_wf + base + OFF_W2A, b2a + (size_t)l * DH);

        const float* xin = (l == 0) ? node : p_gx;
        g4_kernel<<<dim3(DN / 128, MT_N), 256, SMEM_TOTAL>>>(
            xin, p_wf + base + OFF_W2B, b2b + (size_t)l * DN,
            last ? out : p_gx, last);
    }
}

// round 16
// speedup vs baseline: 1.1488x; 1.1488x over previous
#include <cuda_runtime.h>
#include <cuda_fp16.h>
#include <cstdint>

#define N_NODES 20000
#define N_EDGES 100000
#define DN 256
#define DE 256
#define DH 512
#define NLAYERS 2

// ---------------- scratch (device globals: allocation-free) ----------------
__device__ __align__(16) uint16_t g_m1f [(size_t)N_EDGES * DH];
__device__ __align__(16) uint16_t g_ef  [(size_t)N_EDGES * DE];
__device__ __align__(16) uint16_t g_xf  [(size_t)N_NODES * DN];
__device__ __align__(16) uint16_t g_aggf[(size_t)N_NODES * DH];
__device__ __align__(16) uint16_t g_hf  [(size_t)N_NODES * DH];
__device__ float g_x  [(size_t)N_NODES * DN];   // fp32 x for residual
__device__ float g_agg[(size_t)N_NODES * DH];   // fp32 atomics accumulator
__device__ float g_cnt[N_NODES];

// transposed fp16 weights [N][K] K-major, per layer (W1b column-permuted)
#define OFF_W1A 0
#define OFF_W1B (DH * (2 * DN + DE))
#define OFF_W2A (OFF_W1B + (2 * DH + DE) * DH)
#define OFF_W2B (OFF_W2A + DH * DH)
#define WT_LAYER (OFF_W2B + DH * DN)
__device__ __align__(16) uint16_t g_Wf[(size_t)NLAYERS * WT_LAYER];

// ---------------- W1b column permutation ----------------
// xm = m[:, :512] + m[:, 768:1280]. Permuted col 2q   = part1 col k(q),
//                                   permuted col 2q+1 = part2 col k(q),
// with, inside each 32-wide q block B: q = B + 4j + t3  <->  k = B + 8*t3 + j.
// This makes each epilogue thread's (even,odd) register pair = (p1_k, p2_k),
// and its 8 j-values hit 8 CONTIGUOUS k -> two red.v4 per row instead of
// eight red.v2. e-slice (orig cols [512,768)) -> permuted cols [1024,1280).
__device__ __forceinline__ int w1b_perm_col(int n) {   // orig -> permuted
    if (n >= 512 && n < 768) return 1024 + (n - 512);
    int part = (n >= 768) ? 1 : 0;
    int k = part ? (n - 768) : n;
    int B = k & ~31, r = k - B;
    int t3 = r >> 3, j = r & 7;
    return 2 * (B + 4 * j + t3) + part;
}
__device__ __forceinline__ int w1b_orig_col(int cg) {  // permuted -> orig
    if (cg >= 1024) return 512 + (cg - 1024);
    int part = cg & 1, q = cg >> 1;
    int B = q & ~31, r = q - B;
    int j = r >> 2, t3 = r & 3;
    return B + 8 * t3 + j + (part ? 768 : 0);
}

// ---------------- helpers ----------------
__device__ __forceinline__ uint32_t smem_to_u32(const void* p) {
    uint32_t a;
    asm("{ .reg .u64 t; cvta.to.shared.u64 t, %1; cvt.u32.u64 %0, t; }"
        : "=r"(a) : "l"(p));
    return a;
}

__device__ __forceinline__ uint32_t f16x2(float x, float y) {
    uint32_t r;
    asm("cvt.rn.f16x2.f32 %0, %1, %2;" : "=r"(r) : "f"(y), "f"(x));
    return r;
}

__device__ __forceinline__ void cp16(uint32_t dst, const void* src) {
    asm volatile("cp.async.ca.shared.global [%0], [%1], 16;"
                 :: "r"(dst), "l"(src) : "memory");
}
#define CP_COMMIT() asm volatile("cp.async.commit_group;" ::: "memory")
#define CP_WAIT2()  asm volatile("cp.async.wait_group 2;" ::: "memory")
#define CP_WAIT1()  asm volatile("cp.async.wait_group 1;" ::: "memory")
#define CP_WAIT0()  asm volatile("cp.async.wait_group 0;" ::: "memory")

__device__ __forceinline__ void ldsm4(uint32_t addr, uint32_t* r) {
    asm volatile("ldmatrix.sync.aligned.m8n8.x4.shared.b16 {%0,%1,%2,%3}, [%4];"
                 : "=r"(r[0]), "=r"(r[1]), "=r"(r[2]), "=r"(r[3]) : "r"(addr));
}

__device__ __forceinline__ void mma_f16(float* c, const uint32_t* a,
                                        uint32_t b0, uint32_t b1) {
    asm volatile("mma.sync.aligned.m16n8k16.row.col.f32.f16.f16.f32 "
                 "{%0,%1,%2,%3}, {%4,%5,%6,%7}, {%8,%9}, {%0,%1,%2,%3};"
                 : "+f"(c[0]), "+f"(c[1]), "+f"(c[2]), "+f"(c[3])
                 : "r"(a[0]), "r"(a[1]), "r"(a[2]), "r"(a[3]), "r"(b0), "r"(b1));
}

__device__ __forceinline__ void red_add_v4(float* p, float a, float b,
                                           float c, float d) {
    asm volatile("red.global.add.v4.f32 [%0], {%1,%2,%3,%4};"
                 :: "l"(p), "f"(a), "f"(b), "f"(c), "f"(d) : "memory");
}

// ---------------- dynamic smem layout (R14 proven config) ----------------
#define SM_BIAS   0       // 128 floats
#define SM_DST    512     // 128 ints
#define SM_SRC    1024
#define SM_TILES  2048
#define PITCH     80                    // 64B fp16 row + 16B pad
#define TILE_B    (128 * PITCH)         // 10240
#define STAGE_B   (2 * TILE_B)          // A, B
#define NSTAGE    3
#define SMEM_TOTAL (SM_TILES + NSTAGE * STAGE_B)  // 63488 -> 2 CTAs/SM

// ---------------- utility kernels ----------------
__global__ void zero_cnt_kernel() {
    int i = blockIdx.x * blockDim.x + threadIdx.x;
    if (i < N_NODES) g_cnt[i] = 0.f;
}
__global__ void zero_agg_kernel() {
    int i = blockIdx.x * blockDim.x + threadIdx.x;
    if (i < N_NODES * DH / 4)
        ((float4*)g_agg)[i] = make_float4(0.f, 0.f, 0.f, 0.f);
}
__global__ void count_kernel(const int* __restrict__ dstI) {
    int e = blockIdx.x * blockDim.x + threadIdx.x;
    if (e < N_EDGES) atomicAdd(&g_cnt[dstI[e]], 1.f);
}

// fp32 -> fp16 for both inputs in one launch
#define NPX (N_NODES * DN / 2)
#define NPE (N_EDGES * DE / 2)
__global__ void round_inputs_kernel(const float* __restrict__ node,
                                    const float* __restrict__ edge,
                                    uint16_t* __restrict__ xf,
                                    uint16_t* __restrict__ ef) {
    int i = blockIdx.x * blockDim.x + threadIdx.x;
    if (i < NPX) {
        float2 v = ((const float2*)node)[i];
        ((uint32_t*)xf)[i] = f16x2(v.x, v.y);
    } else if (i < NPX + NPE) {
        int j = i - NPX;
        float2 v = ((const float2*)edge)[j];
        ((uint32_t*)ef)[j] = f16x2(v.x, v.y);
    }
}

// agg: normalize by 1/max(cnt,1), round to fp16, AND re-zero for next layer
__global__ void norm_agg_kernel() {
    int i = blockIdx.x * blockDim.x + threadIdx.x;
    if (i < N_NODES * DH / 2) {
        int row = i >> 8;
        float s = 1.f / fmaxf(g_cnt[row], 1.f);
        float2 v = ((const float2*)g_agg)[i];
        ((uint32_t*)g_aggf)[i] = f16x2(v.x * s, v.y * s);
        ((float2*)g_agg)[i] = make_float2(0.f, 0.f);
    }
}

// ALL weight transposes in one launch. W [K][N] -> Wf [N][K] fp16.
// W1b additionally gets the xm column permutation.
#define T_CUM1 384
#define T_CUM2 1024
#define T_CUM3 1280
#define T_TOTAL 1408
__global__ void transpose_all_kernel(const float* __restrict__ W1a,
                                     const float* __restrict__ W1b,
                                     const float* __restrict__ W2a,
                                     const float* __restrict__ W2b,
                                     uint16_t* __restrict__ wf) {
    __shared__ float t[32][33];
    const int l = blockIdx.y;
    int f = blockIdx.x;
    const float* src;
    int K, N, off, isW1b = 0;
    if (f < T_CUM1)      { src = W1a + (size_t)l * 768 * 512;   K = 768; N = 512;  off = OFF_W1A; }
    else if (f < T_CUM2) { f -= T_CUM1; src = W1b + (size_t)l * 512 * 1280; K = 512; N = 1280; off = OFF_W1B; isW1b = 1; }
    else if (f < T_CUM3) { f -= T_CUM2; src = W2a + (size_t)l * 512 * 512;  K = 512; N = 512;  off = OFF_W2A; }
    else                 { f -= T_CUM3; src = W2b + (size_t)l * 512 * 256;  K = 512; N = 256;  off = OFF_W2B; }
    const int tilesN = N / 32;
    const int by = (f / tilesN) * 32;   // K tile
    const int bx = (f % tilesN) * 32;   // N tile
    uint16_t* dst = wf + (size_t)l * WT_LAYER + off;
    const int tx = threadIdx.x, ty = threadIdx.y;
#pragma unroll
    for (int j = 0; j < 32; j += 8)
        t[ty + j][tx] = src[(size_t)(by + ty + j) * N + bx + tx];
    __syncthreads();
#pragma unroll
    for (int j = 0; j < 32; j += 8) {
        int n = bx + ty + j;
        int dcol = isW1b ? w1b_perm_col(n) : n;
        dst[(size_t)dcol * K + by + tx] =
            __half_as_ushort(__float2half_rn(t[tx][ty + j]));
    }
}

// ---------------- fp16 mma.sync mainloop (R14 proven): 3-stage, 2 barriers --
template <int KDIM, class AS>
__device__ __forceinline__ void mainloop_mma(
    char* smem, const uint16_t* __restrict__ Wf,
    int n0, AS asrc, float C[2][8][4])
{
    const int tid = threadIdx.x;
    const int lane = tid & 31, warp = tid >> 5;
    const int wm = warp & 3, wn = warp >> 2;
    const uint32_t sb = smem_to_u32(smem);
    constexpr int NC = KDIM / 32;

    auto issue = [&](int c) {
        const int st = c % NSTAGE;
        const uint32_t base = sb + SM_TILES + st * STAGE_B;
#pragma unroll
        for (int halfp = 0; halfp < 2; ++halfp) {
            int id = tid + halfp * 256;
            int row = id >> 2, seg = id & 3;
            int kg = c * 32 + seg * 8;
            uint32_t off = (uint32_t)row * PITCH + seg * 16;
            cp16(base + off, asrc(row, kg));
            cp16(base + TILE_B + off, Wf + (size_t)(n0 + row) * KDIM + kg);
        }
        CP_COMMIT();
    };

    issue(0);
    if (NC > 1) issue(1);
    if (NC > 2) issue(2);

    const int lrow = lane & 15;
    const int lk = (lane >> 4) * 16;

    for (int c = 0; c < NC; ++c) {
        int rem = NC - 1 - c;
        if (rem >= 2) CP_WAIT2(); else if (rem == 1) CP_WAIT1(); else CP_WAIT0();
        __syncthreads();
        const int st = c % NSTAGE;
        const uint32_t sA = sb + SM_TILES + st * STAGE_B;
        const uint32_t sB = sA + TILE_B;
#pragma unroll
        for (int ks = 0; ks < 2; ++ks) {
            uint32_t a[2][4];
#pragma unroll
            for (int i = 0; i < 2; ++i) {
                uint32_t ao = (uint32_t)(32 * wm + 16 * i + lrow) * PITCH + ks * 32 + lk;
                ldsm4(sA + ao, a[i]);
            }
#pragma unroll
            for (int g = 0; g < 4; ++g) {
                uint32_t bo = (uint32_t)(64 * wn + 16 * g + lrow) * PITCH + ks * 32 + lk;
                uint32_t b[4];
                ldsm4(sB + bo, b);
#pragma unroll
                for (int i = 0; i < 2; ++i) {
                    mma_f16(C[i][2 * g],     a[i], b[0], b[2]);
                    mma_f16(C[i][2 * g + 1], a[i], b[1], b[3]);
                }
            }
        }
        __syncthreads();
        if (c + NSTAGE < NC) issue(c + NSTAGE);
    }
}

#define ZERO_C() \
    float C[2][8][4]; \
    _Pragma("unroll") for (int i = 0; i < 2; ++i) \
    _Pragma("unroll") for (int j = 0; j < 8; ++j) \
    _Pragma("unroll") for (int q = 0; q < 4; ++q) C[i][j][q] = 0.f;

// ============================================================================
// GEMM1: m1 = relu([x[dst]|e|x[src]] @ W1a + b1a) -> fp16 m1f
// ============================================================================
__global__ void __launch_bounds__(256, 2) g1_kernel(
    const int* __restrict__ srcI, const int* __restrict__ dstI,
    const uint16_t* __restrict__ Wf, const float* __restrict__ bias)
{
    extern __shared__ char smem[];
    const int tid = threadIdx.x;
    const int n0 = blockIdx.x * 128, m0 = blockIdx.y * 128;
    float* biasS = (float*)(smem + SM_BIAS);
    int* sDst = (int*)(smem + SM_DST);
    int* sSrc = (int*)(smem + SM_SRC);
    if (tid < 128) {
        biasS[tid] = bias[n0 + tid];
        int r = min(m0 + tid, N_EDGES - 1);
        sDst[tid] = dstI[r];
        sSrc[tid] = srcI[r];
    }
    __syncthreads();

    ZERO_C();
    auto asrc = [&](int row, int kg) -> const uint16_t* {
        int r = min(m0 + row, N_EDGES - 1);
        if (kg < DN)      return g_xf + (size_t)sDst[row] * DN + kg;
        if (kg < DN + DE) return g_ef + (size_t)r * DE + (kg - DN);
        return g_xf + (size_t)sSrc[row] * DN + (kg - DN - DE);
    };
    mainloop_mma<2 * DN + DE>(smem, Wf, n0, asrc, C);

    const int lane = tid & 31, warp = tid >> 5;
    const int wm = warp & 3, wn = warp >> 2;
#pragma unroll
    for (int i = 0; i < 2; ++i)
#pragma unroll
    for (int h = 0; h < 2; ++h) {
        int rl = 32 * wm + 16 * i + 8 * h + (lane >> 2);
        int r = m0 + rl;
        if (r >= N_EDGES) continue;
#pragma unroll
        for (int j = 0; j < 8; ++j) {
            int cl = 64 * wn + 8 * j + 2 * (lane & 3);
            float ox = fmaxf(C[i][j][2 * h + 0] + biasS[cl + 0], 0.f);
            float oy = fmaxf(C[i][j][2 * h + 1] + biasS[cl + 1], 0.f);
            ((uint32_t*)g_m1f)[((size_t)r * DH + n0 + cl) >> 1] = f16x2(ox, oy);
        }
    }
}

// ============================================================================
// GEMM2: relu(m1 @ W1b' + b1b)   (E x 512)@(512 x 1280), W1b column-permuted.
// permuted cols [0,1024): (p1,p2) pairs -> xm in-register -> red.v4 to agg
// permuted cols [1024,1280): new_e
// ============================================================================
__global__ void __launch_bounds__(256, 2) g2_kernel(
    const int* __restrict__ dstI,
    const uint16_t* __restrict__ Wf, const float* __restrict__ bias,
    float* __restrict__ eoutF, int last)
{
    extern __shared__ char smem[];
    const int tid = threadIdx.x;
    const int n0 = blockIdx.x * 128, m0 = blockIdx.y * 128;
    float* biasS = (float*)(smem + SM_BIAS);
    int* sDst = (int*)(smem + SM_DST);
    if (tid < 128) {
        biasS[tid] = bias[w1b_orig_col(n0 + tid)];
        sDst[tid] = dstI[min(m0 + tid, N_EDGES - 1)];
    }
    __syncthreads();

    ZERO_C();
    auto asrc = [&](int row, int kg) -> const uint16_t* {
        size_t r = (size_t)min(m0 + row, N_EDGES - 1);
        return g_m1f + r * DH + kg;
    };
    mainloop_mma<DH>(smem, Wf, n0, asrc, C);

    const int lane = tid & 31, warp = tid >> 5;
    const int wm = warp & 3, wn = warp >> 2;
    const int t3 = lane & 3;
    const bool xm_region = (n0 < 1024);
#pragma unroll
    for (int i = 0; i < 2; ++i)
#pragma unroll
    for (int h = 0; h < 2; ++h) {
        int rl = 32 * wm + 16 * i + 8 * h + (lane >> 2);
        int r = m0 + rl;
        if (r >= N_EDGES) continue;
        if (xm_region) {
            float xmv[8];
#pragma unroll
            for (int j = 0; j < 8; ++j) {
                int cl = 64 * wn + 8 * j + 2 * t3;
                float ox = fmaxf(C[i][j][2 * h + 0] + biasS[cl + 0], 0.f);
                float oy = fmaxf(C[i][j][2 * h + 1] + biasS[cl + 1], 0.f);
                xmv[j] = ox + oy;   // p1_k + p2_k, k = n0/2 + 32*wn + 8*t3 + j
            }
            float* ap = g_agg + (size_t)sDst[rl] * DH
                      + (n0 >> 1) + 32 * wn + 8 * t3;
            red_add_v4(ap,     xmv[0], xmv[1], xmv[2], xmv[3]);
            red_add_v4(ap + 4, xmv[4], xmv[5], xmv[6], xmv[7]);
        } else {
#pragma unroll
            for (int j = 0; j < 8; ++j) {
                int cl = 64 * wn + 8 * j + 2 * t3;
                float ox = fmaxf(C[i][j][2 * h + 0] + biasS[cl + 0], 0.f);
                float oy = fmaxf(C[i][j][2 * h + 1] + biasS[cl + 1], 0.f);
                size_t eoff = (size_t)r * DE + (n0 - 1024) + cl;
                if (last) *(float2*)(eoutF + eoff) = make_float2(ox, oy);
                else      ((uint32_t*)g_ef)[eoff >> 1] = f16x2(ox, oy);
            }
        }
    }
}

// ============================================================================
// GEMM3: h = relu(aggn @ W2a + b2a) -> fp16 hf   (N x 512)@(512 x 512)
// ============================================================================
__global__ void __launch_bounds__(256, 2) g3_kernel(
    const uint16_t* __restrict__ Wf, const float* __restrict__ bias)
{
    extern __shared__ char smem[];
    const int tid = threadIdx.x;
    const int n0 = blockIdx.x * 128, m0 = blockIdx.y * 128;
    float* biasS = (float*)(smem + SM_BIAS);
    if (tid < 128) biasS[tid] = bias[n0 + tid];
    __syncthreads();

    ZERO_C();
    auto asrc = [&](int row, int kg) -> const uint16_t* {
        size_t r = (size_t)min(m0 + row, N_NODES - 1);
        return g_aggf + r * DH + kg;
    };
    mainloop_mma<DH>(smem, Wf, n0, asrc, C);

    const int lane = tid & 31, warp = tid >> 5;
    const int wm = warp & 3, wn = warp >> 2;
#pragma unroll
    for (int i = 0; i < 2; ++i)
#pragma unroll
    for (int h = 0; h < 2; ++h) {
        int rl = 32 * wm + 16 * i + 8 * h + (lane >> 2);
        int r = m0 + rl;
        if (r >= N_NODES) continue;
#pragma unroll
        for (int j = 0; j < 8; ++j) {
            int cl = 64 * wn + 8 * j + 2 * (lane & 3);
            float ox = fmaxf(C[i][j][2 * h + 0] + biasS[cl + 0], 0.f);
            float oy = fmaxf(C[i][j][2 * h + 1] + biasS[cl + 1], 0.f);
            ((uint32_t*)g_hf)[((size_t)r * DH + n0 + cl) >> 1] = f16x2(ox, oy);
        }
    }
}

// ============================================================================
// GEMM4: new_x = x + (h @ W2b + b2b)  [+relu, + fp16 copy for next layer]
// ============================================================================
__global__ void __launch_bounds__(256, 2) g4_kernel(
    const float* __restrict__ xin,
    const uint16_t* __restrict__ Wf, const float* __restrict__ bias,
    float* __restrict__ xoutF, int last)
{
    extern __shared__ char smem[];
    const int tid = threadIdx.x;
    const int n0 = blockIdx.x * 128, m0 = blockIdx.y * 128;
    float* biasS = (float*)(smem + SM_BIAS);
    if (tid < 128) biasS[tid] = bias[n0 + tid];
    __syncthreads();

    ZERO_C();
    auto asrc = [&](int row, int kg) -> const uint16_t* {
        size_t r = (size_t)min(m0 + row, N_NODES - 1);
        return g_hf + r * DH + kg;
    };
    mainloop_mma<DH>(smem, Wf, n0, asrc, C);

    const int lane = tid & 31, warp = tid >> 5;
    const int wm = warp & 3, wn = warp >> 2;
#pragma unroll
    for (int i = 0; i < 2; ++i)
#pragma unroll
    for (int h = 0; h < 2; ++h) {
        int rl = 32 * wm + 16 * i + 8 * h + (lane >> 2);
        int r = m0 + rl;
        if (r >= N_NODES) continue;
        const float* xrow = xin + (size_t)r * DN + n0;
#pragma unroll
        for (int j = 0; j < 8; ++j) {
            int cl = 64 * wn + 8 * j + 2 * (lane & 3);
            float2 xv = *(const float2*)(xrow + cl);
            float ox = C[i][j][2 * h + 0] + biasS[cl + 0] + xv.x;
            float oy = C[i][j][2 * h + 1] + biasS[cl + 1] + xv.y;
            size_t xoff = (size_t)r * DN + n0 + cl;
            if (last) {
                *(float2*)(xoutF + xoff) = make_float2(ox, oy);
            } else {
                ox = fmaxf(ox, 0.f); oy = fmaxf(oy, 0.f);
                *(float2*)(xoutF + xoff) = make_float2(ox, oy);
                ((uint32_t*)g_xf)[xoff >> 1] = f16x2(ox, oy);
            }
        }
    }
}

// ============================================================================
extern "C" void kernel_launch(void* const* d_in, const int* in_sizes, int n_in,
                              void* d_out, int out_size)
{
    (void)in_sizes; (void)n_in; (void)out_size;
    const float* node = (const float*)d_in[0];
    const float* edge = (const float*)d_in[1];
    const int*   eidx = (const int*)  d_in[2];
    const float* W1a  = (const float*)d_in[3];
    const float* b1a  = (const float*)d_in[4];
    const float* W1b  = (const float*)d_in[5];
    const float* b1b  = (const float*)d_in[6];
    const float* W2a  = (const float*)d_in[7];
    const float* b2a  = (const float*)d_in[8];
    const float* W2b  = (const float*)d_in[9];
    const float* b2b  = (const float*)d_in[10];
    float* out = (float*)d_out;

    const int* srcI = eidx;
    const int* dstI = eidx + N_EDGES;

    cudaFuncSetAttribute(g1_kernel, cudaFuncAttributeMaxDynamicSharedMemorySize, SMEM_TOTAL);
    cudaFuncSetAttribute(g2_kernel, cudaFuncAttributeMaxDynamicSharedMemorySize, SMEM_TOTAL);
    cudaFuncSetAttribute(g3_kernel, cudaFuncAttributeMaxDynamicSharedMemorySize, SMEM_TOTAL);
    cudaFuncSetAttribute(g4_kernel, cudaFuncAttributeMaxDynamicSharedMemorySize, SMEM_TOTAL);

    void* t;
    cudaGetSymbolAddress(&t, g_x);  float* p_gx = (float*)t;
    cudaGetSymbolAddress(&t, g_xf); uint16_t* p_xf = (uint16_t*)t;
    cudaGetSymbolAddress(&t, g_ef); uint16_t* p_ef = (uint16_t*)t;
    cudaGetSymbolAddress(&t, g_Wf); uint16_t* p_wf = (uint16_t*)t;

    // setup
    round_inputs_kernel<<<(NPX + NPE + 255) / 256, 256>>>(node, edge, p_xf, p_ef);
    transpose_all_kernel<<<dim3(T_TOTAL, NLAYERS), dim3(32, 8)>>>(
        W1a, W1b, W2a, W2b, p_wf);
    zero_cnt_kernel<<<(N_NODES + 255) / 256, 256>>>();
    count_kernel<<<(N_EDGES + 255) / 256, 256>>>(dstI);
    zero_agg_kernel<<<(N_NODES * DH / 4 + 255) / 256, 256>>>();  // once; norm_agg re-zeros

    const int MT_E = (N_EDGES + 127) / 128;  // 782
    const int MT_N = (N_NODES + 127) / 128;  // 157

    for (int l = 0; l < NLAYERS; ++l) {
        const int last = (l == NLAYERS - 1) ? 1 : 0;
        size_t base = (size_t)l * WT_LAYER;

        g1_kernel<<<dim3(DH / 128, MT_E), 256, SMEM_TOTAL>>>(
            srcI, dstI, p_wf + base + OFF_W1A, b1a + (size_t)l * DH);

        g2_kernel<<<dim3((2 * DH + DE) / 128, MT_E), 256, SMEM_TOTAL>>>(
            dstI, p_wf + base + OFF_W1B, b1b + (size_t)l * (2 * DH + DE),
            last ? (out + (size_t)N_NODES * DN) : nullptr, last);

        norm_agg_kernel<<<(N_NODES * DH / 2 + 255) / 256, 256>>>();

        g3_kernel<<<dim3(DH / 128, MT_N), 256, SMEM_TOTAL>>>(
            p_wf + base + OFF_W2A, b2a + (size_t)l * DH);

        const float* xin = (l == 0) ? node : p_gx;
        g4_kernel<<<dim3(DN / 128, MT_N), 256, SMEM_TOTAL>>>(
            xin, p_wf + base + OFF_W2B, b2b + (size_t)l * DN,
            last ? out : p_gx, last);
    }
}

// round 17
// speedup vs baseline: 1.2276x; 1.0686x over previous
#include <cuda_runtime.h>
#include <cuda_fp16.h>
#include <cstdint>

#define N_NODES 20000
#define N_EDGES 100000
#define DN 256
#define DE 256
#define DH 512
#define NLAYERS 2

// ---------------- scratch (device globals: allocation-free) ----------------
__device__ __align__(16) uint16_t g_m1f [(size_t)N_EDGES * DH];
__device__ __align__(16) uint16_t g_ef  [(size_t)N_EDGES * DE];
__device__ __align__(16) uint16_t g_xf  [(size_t)N_NODES * DN];
__device__ __align__(16) uint16_t g_aggf[(size_t)N_NODES * DH];
__device__ __align__(16) uint16_t g_hf  [(size_t)N_NODES * DH];
__device__ float g_x  [(size_t)N_NODES * DN];   // fp32 x for residual
__device__ float g_agg[(size_t)N_NODES * DH];   // fp32 atomics accumulator
__device__ float g_cnt[N_NODES];

// transposed fp16 weights [N][K] K-major, per layer (W1b column-permuted)
#define OFF_W1A 0
#define OFF_W1B (DH * (2 * DN + DE))
#define OFF_W2A (OFF_W1B + (2 * DH + DE) * DH)
#define OFF_W2B (OFF_W2A + DH * DH)
#define WT_LAYER (OFF_W2B + DH * DN)
__device__ __align__(16) uint16_t g_Wf[(size_t)NLAYERS * WT_LAYER];

// ---------------- W1b column permutation (validated R16) ----------------
__device__ __forceinline__ int w1b_perm_col(int n) {   // orig -> permuted
    if (n >= 512 && n < 768) return 1024 + (n - 512);
    int part = (n >= 768) ? 1 : 0;
    int k = part ? (n - 768) : n;
    int B = k & ~31, r = k - B;
    int t3 = r >> 3, j = r & 7;
    return 2 * (B + 4 * j + t3) + part;
}
__device__ __forceinline__ int w1b_orig_col(int cg) {  // permuted -> orig
    if (cg >= 1024) return 512 + (cg - 1024);
    int part = cg & 1, q = cg >> 1;
    int B = q & ~31, r = q - B;
    int j = r >> 2, t3 = r & 3;
    return B + 8 * t3 + j + (part ? 768 : 0);
}

// ---------------- helpers ----------------
__device__ __forceinline__ uint32_t smem_to_u32(const void* p) {
    uint32_t a;
    asm("{ .reg .u64 t; cvta.to.shared.u64 t, %1; cvt.u32.u64 %0, t; }"
        : "=r"(a) : "l"(p));
    return a;
}

__device__ __forceinline__ uint32_t f16x2(float x, float y) {
    uint32_t r;
    asm("cvt.rn.f16x2.f32 %0, %1, %2;" : "=r"(r) : "f"(y), "f"(x));
    return r;
}

__device__ __forceinline__ void cp16(uint32_t dst, const void* src) {
    asm volatile("cp.async.ca.shared.global [%0], [%1], 16;"
                 :: "r"(dst), "l"(src) : "memory");
}
#define CP_COMMIT() asm volatile("cp.async.commit_group;" ::: "memory")
#define CP_WAIT1()  asm volatile("cp.async.wait_group 1;" ::: "memory")
#define CP_WAIT0()  asm volatile("cp.async.wait_group 0;" ::: "memory")

__device__ __forceinline__ void ldsm4(uint32_t addr, uint32_t* r) {
    asm volatile("ldmatrix.sync.aligned.m8n8.x4.shared.b16 {%0,%1,%2,%3}, [%4];"
                 : "=r"(r[0]), "=r"(r[1]), "=r"(r[2]), "=r"(r[3]) : "r"(addr));
}

__device__ __forceinline__ void mma_f16(float* c, const uint32_t* a,
                                        uint32_t b0, uint32_t b1) {
    asm volatile("mma.sync.aligned.m16n8k16.row.col.f32.f16.f16.f32 "
                 "{%0,%1,%2,%3}, {%4,%5,%6,%7}, {%8,%9}, {%0,%1,%2,%3};"
                 : "+f"(c[0]), "+f"(c[1]), "+f"(c[2]), "+f"(c[3])
                 : "r"(a[0]), "r"(a[1]), "r"(a[2]), "r"(a[3]), "r"(b0), "r"(b1));
}

__device__ __forceinline__ void red_add_v4(float* p, float a, float b,
                                           float c, float d) {
    asm volatile("red.global.add.v4.f32 [%0], {%1,%2,%3,%4};"
                 :: "l"(p), "f"(a), "f"(b), "f"(c), "f"(d) : "memory");
}

// ---------------- dynamic smem layout: BK=64, 2 stages ----------------
#define SM_BIAS   0       // 128 floats
#define SM_DST    512     // 128 ints
#define SM_SRC    1024
#define SM_TILES  2048
#define PITCH     144                   // 128B fp16 row (64 halves) + 16B pad
#define TILE_B    (128 * PITCH)         // 18432
#define STAGE_B   (2 * TILE_B)          // A, B = 36864
#define NSTAGE    2
#define SMEM_TOTAL (SM_TILES + NSTAGE * STAGE_B)  // 75776 -> 2 CTAs/SM

// ---------------- utility kernels ----------------
__global__ void zero_cnt_kernel() {
    int i = blockIdx.x * blockDim.x + threadIdx.x;
    if (i < N_NODES) g_cnt[i] = 0.f;
}
__global__ void zero_agg_kernel() {
    int i = blockIdx.x * blockDim.x + threadIdx.x;
    if (i < N_NODES * DH / 4)
        ((float4*)g_agg)[i] = make_float4(0.f, 0.f, 0.f, 0.f);
}
__global__ void count_kernel(const int* __restrict__ dstI) {
    int e = blockIdx.x * blockDim.x + threadIdx.x;
    if (e < N_EDGES) atomicAdd(&g_cnt[dstI[e]], 1.f);
}

// fp32 -> fp16 for both inputs in one launch
#define NPX (N_NODES * DN / 2)
#define NPE (N_EDGES * DE / 2)
__global__ void round_inputs_kernel(const float* __restrict__ node,
                                    const float* __restrict__ edge,
                                    uint16_t* __restrict__ xf,
                                    uint16_t* __restrict__ ef) {
    int i = blockIdx.x * blockDim.x + threadIdx.x;
    if (i < NPX) {
        float2 v = ((const float2*)node)[i];
        ((uint32_t*)xf)[i] = f16x2(v.x, v.y);
    } else if (i < NPX + NPE) {
        int j = i - NPX;
        float2 v = ((const float2*)edge)[j];
        ((uint32_t*)ef)[j] = f16x2(v.x, v.y);
    }
}

// agg: normalize by 1/max(cnt,1), round to fp16, AND re-zero for next layer
__global__ void norm_agg_kernel() {
    int i = blockIdx.x * blockDim.x + threadIdx.x;
    if (i < N_NODES * DH / 2) {
        int row = i >> 8;
        float s = 1.f / fmaxf(g_cnt[row], 1.f);
        float2 v = ((const float2*)g_agg)[i];
        ((uint32_t*)g_aggf)[i] = f16x2(v.x * s, v.y * s);
        ((float2*)g_agg)[i] = make_float2(0.f, 0.f);
    }
}

// ALL weight transposes in one launch. W [K][N] -> Wf [N][K] fp16.
#define T_CUM1 384
#define T_CUM2 1024
#define T_CUM3 1280
#define T_TOTAL 1408
__global__ void transpose_all_kernel(const float* __restrict__ W1a,
                                     const float* __restrict__ W1b,
                                     const float* __restrict__ W2a,
                                     const float* __restrict__ W2b,
                                     uint16_t* __restrict__ wf) {
    __shared__ float t[32][33];
    const int l = blockIdx.y;
    int f = blockIdx.x;
    const float* src;
    int K, N, off, isW1b = 0;
    if (f < T_CUM1)      { src = W1a + (size_t)l * 768 * 512;   K = 768; N = 512;  off = OFF_W1A; }
    else if (f < T_CUM2) { f -= T_CUM1; src = W1b + (size_t)l * 512 * 1280; K = 512; N = 1280; off = OFF_W1B; isW1b = 1; }
    else if (f < T_CUM3) { f -= T_CUM2; src = W2a + (size_t)l * 512 * 512;  K = 512; N = 512;  off = OFF_W2A; }
    else                 { f -= T_CUM3; src = W2b + (size_t)l * 512 * 256;  K = 512; N = 256;  off = OFF_W2B; }
    const int tilesN = N / 32;
    const int by = (f / tilesN) * 32;   // K tile
    const int bx = (f % tilesN) * 32;   // N tile
    uint16_t* dst = wf + (size_t)l * WT_LAYER + off;
    const int tx = threadIdx.x, ty = threadIdx.y;
#pragma unroll
    for (int j = 0; j < 32; j += 8)
        t[ty + j][tx] = src[(size_t)(by + ty + j) * N + bx + tx];
    __syncthreads();
#pragma unroll
    for (int j = 0; j < 32; j += 8) {
        int n = bx + ty + j;
        int dcol = isW1b ? w1b_perm_col(n) : n;
        dst[(size_t)dcol * K + by + tx] =
            __half_as_ushort(__float2half_rn(t[tx][ty + j]));
    }
}

// ---------------- fp16 mma.sync mainloop: BK=64, 2-stage, 2 barriers/chunk --
// 128x128 CTA tile, 8 warps (4M x 2N), warp tile 32x64.
// Per chunk per thread: 4 A-cp16 + 4 B-cp16; per warp: 24 ldsm + 64 mma.
template <int KDIM, class AS>
__device__ __forceinline__ void mainloop_mma(
    char* smem, const uint16_t* __restrict__ Wf,
    int n0, AS asrc, float C[2][8][4])
{
    const int tid = threadIdx.x;
    const int lane = tid & 31, warp = tid >> 5;
    const int wm = warp & 3, wn = warp >> 2;
    const uint32_t sb = smem_to_u32(smem);
    constexpr int NC = KDIM / 64;
    static_assert(NC >= 2, "pipeline depth");

    auto issue = [&](int c) {
        const int st = c & 1;
        const uint32_t base = sb + SM_TILES + st * STAGE_B;
#pragma unroll
        for (int p = 0; p < 4; ++p) {
            int s = tid + p * 256;             // [0, 1024)
            int row = s >> 3, seg = s & 7;     // 8 x 16B segments per 128B row
            int kg = c * 64 + seg * 8;
            uint32_t off = (uint32_t)row * PITCH + seg * 16;
            cp16(base + off, asrc(row, kg));
            cp16(base + TILE_B + off, Wf + (size_t)(n0 + row) * KDIM + kg);
        }
        CP_COMMIT();
    };

    issue(0);
    issue(1);

    const int lrow = lane & 15;
    const int lk = (lane >> 4) * 16;

    for (int c = 0; c < NC; ++c) {
        if (c + 1 < NC) CP_WAIT1(); else CP_WAIT0();
        __syncthreads();
        const int st = c & 1;
        const uint32_t sA = sb + SM_TILES + st * STAGE_B;
        const uint32_t sB = sA + TILE_B;
#pragma unroll
        for (int ks = 0; ks < 4; ++ks) {
            uint32_t a[2][4];
#pragma unroll
            for (int i = 0; i < 2; ++i) {
                uint32_t ao = (uint32_t)(32 * wm + 16 * i + lrow) * PITCH + ks * 32 + lk;
                ldsm4(sA + ao, a[i]);
            }
#pragma unroll
            for (int g = 0; g < 4; ++g) {
                uint32_t bo = (uint32_t)(64 * wn + 16 * g + lrow) * PITCH + ks * 32 + lk;
                uint32_t b[4];
                ldsm4(sB + bo, b);
#pragma unroll
                for (int i = 0; i < 2; ++i) {
                    mma_f16(C[i][2 * g],     a[i], b[0], b[2]);
                    mma_f16(C[i][2 * g + 1], a[i], b[1], b[3]);
                }
            }
        }
        __syncthreads();   // all warps done reading stage st before overwrite
        if (c + 2 < NC) issue(c + 2);
    }
}

#define ZERO_C() \
    float C[2][8][4]; \
    _Pragma("unroll") for (int i = 0; i < 2; ++i) \
    _Pragma("unroll") for (int j = 0; j < 8; ++j) \
    _Pragma("unroll") for (int q = 0; q < 4; ++q) C[i][j][q] = 0.f;

// ============================================================================
// GEMM1: m1 = relu([x[dst]|e|x[src]] @ W1a + b1a) -> fp16 m1f
// ============================================================================
__global__ void __launch_bounds__(256, 2) g1_kernel(
    const int* __restrict__ srcI, const int* __restrict__ dstI,
    const uint16_t* __restrict__ Wf, const float* __restrict__ bias)
{
    extern __shared__ char smem[];
    const int tid = threadIdx.x;
    const int n0 = blockIdx.x * 128, m0 = blockIdx.y * 128;
    float* biasS = (float*)(smem + SM_BIAS);
    int* sDst = (int*)(smem + SM_DST);
    int* sSrc = (int*)(smem + SM_SRC);
    if (tid < 128) {
        biasS[tid] = bias[n0 + tid];
        int r = min(m0 + tid, N_EDGES - 1);
        sDst[tid] = dstI[r];
        sSrc[tid] = srcI[r];
    }
    __syncthreads();

    ZERO_C();
    auto asrc = [&](int row, int kg) -> const uint16_t* {
        int r = min(m0 + row, N_EDGES - 1);
        if (kg < DN)      return g_xf + (size_t)sDst[row] * DN + kg;
        if (kg < DN + DE) return g_ef + (size_t)r * DE + (kg - DN);
        return g_xf + (size_t)sSrc[row] * DN + (kg - DN - DE);
    };
    mainloop_mma<2 * DN + DE>(smem, Wf, n0, asrc, C);

    const int lane = tid & 31, warp = tid >> 5;
    const int wm = warp & 3, wn = warp >> 2;
#pragma unroll
    for (int i = 0; i < 2; ++i)
#pragma unroll
    for (int h = 0; h < 2; ++h) {
        int rl = 32 * wm + 16 * i + 8 * h + (lane >> 2);
        int r = m0 + rl;
        if (r >= N_EDGES) continue;
#pragma unroll
        for (int j = 0; j < 8; ++j) {
            int cl = 64 * wn + 8 * j + 2 * (lane & 3);
            float ox = fmaxf(C[i][j][2 * h + 0] + biasS[cl + 0], 0.f);
            float oy = fmaxf(C[i][j][2 * h + 1] + biasS[cl + 1], 0.f);
            ((uint32_t*)g_m1f)[((size_t)r * DH + n0 + cl) >> 1] = f16x2(ox, oy);
        }
    }
}

// ============================================================================
// GEMM2: relu(m1 @ W1b' + b1b), W1b column-permuted (xm pairs + e tail)
// ============================================================================
__global__ void __launch_bounds__(256, 2) g2_kernel(
    const int* __restrict__ dstI,
    const uint16_t* __restrict__ Wf, const float* __restrict__ bias,
    float* __restrict__ eoutF, int last)
{
    extern __shared__ char smem[];
    const int tid = threadIdx.x;
    const int n0 = blockIdx.x * 128, m0 = blockIdx.y * 128;
    float* biasS = (float*)(smem + SM_BIAS);
    int* sDst = (int*)(smem + SM_DST);
    if (tid < 128) {
        biasS[tid] = bias[w1b_orig_col(n0 + tid)];
        sDst[tid] = dstI[min(m0 + tid, N_EDGES - 1)];
    }
    __syncthreads();

    ZERO_C();
    auto asrc = [&](int row, int kg) -> const uint16_t* {
        size_t r = (size_t)min(m0 + row, N_EDGES - 1);
        return g_m1f + r * DH + kg;
    };
    mainloop_mma<DH>(smem, Wf, n0, asrc, C);

    const int lane = tid & 31, warp = tid >> 5;
    const int wm = warp & 3, wn = warp >> 2;
    const int t3 = lane & 3;
    const bool xm_region = (n0 < 1024);
#pragma unroll
    for (int i = 0; i < 2; ++i)
#pragma unroll
    for (int h = 0; h < 2; ++h) {
        int rl = 32 * wm + 16 * i + 8 * h + (lane >> 2);
        int r = m0 + rl;
        if (r >= N_EDGES) continue;
        if (xm_region) {
            float xmv[8];
#pragma unroll
            for (int j = 0; j < 8; ++j) {
                int cl = 64 * wn + 8 * j + 2 * t3;
                float ox = fmaxf(C[i][j][2 * h + 0] + biasS[cl + 0], 0.f);
                float oy = fmaxf(C[i][j][2 * h + 1] + biasS[cl + 1], 0.f);
                xmv[j] = ox + oy;
            }
            float* ap = g_agg + (size_t)sDst[rl] * DH
                      + (n0 >> 1) + 32 * wn + 8 * t3;
            red_add_v4(ap,     xmv[0], xmv[1], xmv[2], xmv[3]);
            red_add_v4(ap + 4, xmv[4], xmv[5], xmv[6], xmv[7]);
        } else {
#pragma unroll
            for (int j = 0; j < 8; ++j) {
                int cl = 64 * wn + 8 * j + 2 * t3;
                float ox = fmaxf(C[i][j][2 * h + 0] + biasS[cl + 0], 0.f);
                float oy = fmaxf(C[i][j][2 * h + 1] + biasS[cl + 1], 0.f);
                size_t eoff = (size_t)r * DE + (n0 - 1024) + cl;
                if (last) *(float2*)(eoutF + eoff) = make_float2(ox, oy);
                else      ((uint32_t*)g_ef)[eoff >> 1] = f16x2(ox, oy);
            }
        }
    }
}

// ============================================================================
// GEMM3: h = relu(aggn @ W2a + b2a) -> fp16 hf
// ============================================================================
__global__ void __launch_bounds__(256, 2) g3_kernel(
    const uint16_t* __restrict__ Wf, const float* __restrict__ bias)
{
    extern __shared__ char smem[];
    const int tid = threadIdx.x;
    const int n0 = blockIdx.x * 128, m0 = blockIdx.y * 128;
    float* biasS = (float*)(smem + SM_BIAS);
    if (tid < 128) biasS[tid] = bias[n0 + tid];
    __syncthreads();

    ZERO_C();
    auto asrc = [&](int row, int kg) -> const uint16_t* {
        size_t r = (size_t)min(m0 + row, N_NODES - 1);
        return g_aggf + r * DH + kg;
    };
    mainloop_mma<DH>(smem, Wf, n0, asrc, C);

    const int lane = tid & 31, warp = tid >> 5;
    const int wm = warp & 3, wn = warp >> 2;
#pragma unroll
    for (int i = 0; i < 2; ++i)
#pragma unroll
    for (int h = 0; h < 2; ++h) {
        int rl = 32 * wm + 16 * i + 8 * h + (lane >> 2);
        int r = m0 + rl;
        if (r >= N_NODES) continue;
#pragma unroll
        for (int j = 0; j < 8; ++j) {
            int cl = 64 * wn + 8 * j + 2 * (lane & 3);
            float ox = fmaxf(C[i][j][2 * h + 0] + biasS[cl + 0], 0.f);
            float oy = fmaxf(C[i][j][2 * h + 1] + biasS[cl + 1], 0.f);
            ((uint32_t*)g_hf)[((size_t)r * DH + n0 + cl) >> 1] = f16x2(ox, oy);
        }
    }
}

// ============================================================================
// GEMM4: new_x = x + (h @ W2b + b2b)  [+relu, + fp16 copy for next layer]
// ============================================================================
__global__ void __launch_bounds__(256, 2) g4_kernel(
    const float* __restrict__ xin,
    const uint16_t* __restrict__ Wf, const float* __restrict__ bias,
    float* __restrict__ xoutF, int last)
{
    extern __shared__ char smem[];
    const int tid = threadIdx.x;
    const int n0 = blockIdx.x * 128, m0 = blockIdx.y * 128;
    float* biasS = (float*)(smem + SM_BIAS);
    if (tid < 128) biasS[tid] = bias[n0 + tid];
    __syncthreads();

    ZERO_C();
    auto asrc = [&](int row, int kg) -> const uint16_t* {
        size_t r = (size_t)min(m0 + row, N_NODES - 1);
        return g_hf + r * DH + kg;
    };
    mainloop_mma<DH>(smem, Wf, n0, asrc, C);

    const int lane = tid & 31, warp = tid >> 5;
    const int wm = warp & 3, wn = warp >> 2;
#pragma unroll
    for (int i = 0; i < 2; ++i)
#pragma unroll
    for (int h = 0; h < 2; ++h) {
        int rl = 32 * wm + 16 * i + 8 * h + (lane >> 2);
        int r = m0 + rl;
        if (r >= N_NODES) continue;
        const float* xrow = xin + (size_t)r * DN + n0;
#pragma unroll
        for (int j = 0; j < 8; ++j) {
            int cl = 64 * wn + 8 * j + 2 * (lane & 3);
            float2 xv = *(const float2*)(xrow + cl);
            float ox = C[i][j][2 * h + 0] + biasS[cl + 0] + xv.x;
            float oy = C[i][j][2 * h + 1] + biasS[cl + 1] + xv.y;
            size_t xoff = (size_t)r * DN + n0 + cl;
            if (last) {
                *(float2*)(xoutF + xoff) = make_float2(ox, oy);
            } else {
                ox = fmaxf(ox, 0.f); oy = fmaxf(oy, 0.f);
                *(float2*)(xoutF + xoff) = make_float2(ox, oy);
                ((uint32_t*)g_xf)[xoff >> 1] = f16x2(ox, oy);
            }
        }
    }
}

// ============================================================================
extern "C" void kernel_launch(void* const* d_in, const int* in_sizes, int n_in,
                              void* d_out, int out_size)
{
    (void)in_sizes; (void)n_in; (void)out_size;
    const float* node = (const float*)d_in[0];
    const float* edge = (const float*)d_in[1];
    const int*   eidx = (const int*)  d_in[2];
    const float* W1a  = (const float*)d_in[3];
    const float* b1a  = (const float*)d_in[4];
    const float* W1b  = (const float*)d_in[5];
    const float* b1b  = (const float*)d_in[6];
    const float* W2a  = (const float*)d_in[7];
    const float* b2a  = (const float*)d_in[8];
    const float* W2b  = (const float*)d_in[9];
    const float* b2b  = (const float*)d_in[10];
    float* out = (float*)d_out;

    const int* srcI = eidx;
    const int* dstI = eidx + N_EDGES;

    cudaFuncSetAttribute(g1_kernel, cudaFuncAttributeMaxDynamicSharedMemorySize, SMEM_TOTAL);
    cudaFuncSetAttribute(g2_kernel, cudaFuncAttributeMaxDynamicSharedMemorySize, SMEM_TOTAL);
    cudaFuncSetAttribute(g3_kernel, cudaFuncAttributeMaxDynamicSharedMemorySize, SMEM_TOTAL);
    cudaFuncSetAttribute(g4_kernel, cudaFuncAttributeMaxDynamicSharedMemorySize, SMEM_TOTAL);

    void* t;
    cudaGetSymbolAddress(&t, g_x);  float* p_gx = (float*)t;
    cudaGetSymbolAddress(&t, g_xf); uint16_t* p_xf = (uint16_t*)t;
    cudaGetSymbolAddress(&t, g_ef); uint16_t* p_ef = (uint16_t*)t;
    cudaGetSymbolAddress(&t, g_Wf); uint16_t* p_wf = (uint16_t*)t;

    // setup
    round_inputs_kernel<<<(NPX + NPE + 255) / 256, 256>>>(node, edge, p_xf, p_ef);
    transpose_all_kernel<<<dim3(T_TOTAL, NLAYERS), dim3(32, 8)>>>(
        W1a, W1b, W2a, W2b, p_wf);
    zero_cnt_kernel<<<(N_NODES + 255) / 256, 256>>>();
    count_kernel<<<(N_EDGES + 255) / 256, 256>>>(dstI);
    zero_agg_kernel<<<(N_NODES * DH / 4 + 255) / 256, 256>>>();  // once; norm_agg re-zeros

    const int MT_E = (N_EDGES + 127) / 128;  // 782
    const int MT_N = (N_NODES + 127) / 128;  // 157

    for (int l = 0; l < NLAYERS; ++l) {
        const int last = (l == NLAYERS - 1) ? 1 : 0;
        size_t base = (size_t)l * WT_LAYER;

        g1_kernel<<<dim3(DH / 128, MT_E), 256, SMEM_TOTAL>>>(
            srcI, dstI, p_wf + base + OFF_W1A, b1a + (size_t)l * DH);

        g2_kernel<<<dim3((2 * DH + DE) / 128, MT_E), 256, SMEM_TOTAL>>>(
            dstI, p_wf + base + OFF_W1B, b1b + (size_t)l * (2 * DH + DE),
            last ? (out + (size_t)N_NODES * DN) : nullptr, last);

        norm_agg_kernel<<<(N_NODES * DH / 2 + 255) / 256, 256>>>();

        g3_kernel<<<dim3(DH / 128, MT_N), 256, SMEM_TOTAL>>>(
            p_wf + base + OFF_W2A, b2a + (size_t)l * DH);

        const float* xin = (l == 0) ? node : p_gx;
        g4_kernel<<<dim3(DN / 128, MT_N), 256, SMEM_TOTAL>>>(
            xin, p_wf + base + OFF_W2B, b2b + (size_t)l * DN,
            last ? out : p_gx, last);
    }
}